// round 1
// baseline (speedup 1.0000x reference)
#include <cuda_runtime.h>
#include <cstdint>
#include <math.h>

#define NLY 8
#define Hd 768
#define Ed 1536
#define Nst 16
#define Rr 4
#define Kc 4
#define Cc 3
#define Bb 2
#define Ll 2048
#define Mrows (Bb*Ll)        // 4096
#define DBC (Rr+2*Nst)       // 36
#define TWO_E (2*Ed)         // 3072

// ---------------- scratch (device globals; no allocation allowed) ------------
__device__ float g_hs  [Mrows*Hd];
__device__ float g_x   [Mrows*Hd];
__device__ float g_proj[Mrows*TWO_E];
__device__ float g_u   [Mrows*Ed];
__device__ float g_dbc [Mrows*DBC];
__device__ float g_ys  [Mrows*Ed];
__device__ float g_acc [Mrows*Hd];
__device__ float g_yb  [Mrows*Hd];
__device__ float g_yb2 [Mrows*Hd];

// ---------------- embedding --------------------------------------------------
__global__ void embed_kernel(const int* __restrict__ ids, const float* __restrict__ tok,
                             const float* __restrict__ pos, float* __restrict__ hs)
{
    int idx = blockIdx.x*blockDim.x + threadIdx.x;
    if (idx >= Mrows*Hd) return;
    int h = idx % Hd;
    int m = idx / Hd;
    int l = m % Ll;
    int id = ids[m];
    hs[idx] = tok[(size_t)id*Hd + h] + pos[(size_t)l*Hd + h];
}

// ---------------- layernorm (one block per row) ------------------------------
__global__ void ln_kernel(const float* __restrict__ in, const float* __restrict__ w,
                          const float* __restrict__ b, float* __restrict__ out)
{
    int row = blockIdx.x;
    const float* x = in + (size_t)row*Hd;
    float s = 0.f, s2 = 0.f;
    for (int i = threadIdx.x; i < Hd; i += 256) { float v = x[i]; s += v; s2 += v*v; }
    #pragma unroll
    for (int o = 16; o; o >>= 1) {
        s  += __shfl_xor_sync(0xffffffffu, s,  o);
        s2 += __shfl_xor_sync(0xffffffffu, s2, o);
    }
    __shared__ float sa[8], sb[8];
    __shared__ float sh_mean, sh_inv;
    int wi = threadIdx.x >> 5;
    if ((threadIdx.x & 31) == 0) { sa[wi] = s; sb[wi] = s2; }
    __syncthreads();
    if (threadIdx.x == 0) {
        float ts = 0.f, t2 = 0.f;
        #pragma unroll
        for (int i = 0; i < 8; i++) { ts += sa[i]; t2 += sb[i]; }
        float m  = ts / (float)Hd;
        float var = t2 / (float)Hd - m*m;
        sh_mean = m;
        sh_inv  = rsqrtf(var + 1e-5f);
    }
    __syncthreads();
    float mean = sh_mean, inv = sh_inv;
    for (int i = threadIdx.x; i < Hd; i += 256)
        out[(size_t)row*Hd + i] = (x[i] - mean) * inv * w[i] + b[i];
}

// ---------------- generic fp32 GEMM: C = act(A[M,K] @ W[K,N] + bias [+add]) --
// 128x128 tile, BK=8, 256 threads, 8x8 per thread (split-register mapping).
// M, N, K must be multiples of 128/128/8 (true for all call sites).
template<int ACT, int ACCU, int HASADD>
__global__ __launch_bounds__(256)
void gemm128(const float* __restrict__ A, const float* __restrict__ W,
             const float* __restrict__ bias, const float* __restrict__ add,
             float* __restrict__ C, int M, int K, int N)
{
    __shared__ float As[8][128];
    __shared__ float Bs[8][128];
    int tid = threadIdx.x;
    int tx = tid & 15, ty = tid >> 4;
    int brow = blockIdx.y << 7, bcol = blockIdx.x << 7;

    float acc[8][8];
    #pragma unroll
    for (int i = 0; i < 8; i++)
        #pragma unroll
        for (int j = 0; j < 8; j++) acc[i][j] = 0.f;

    const int ar = tid >> 1, ac = (tid & 1) * 4;
    const int br = tid >> 5, bc = (tid & 31) * 4;

    for (int k0 = 0; k0 < K; k0 += 8) {
        float4 av = *(const float4*)(A + (size_t)(brow + ar)*K + k0 + ac);
        float4 bv = *(const float4*)(W + (size_t)(k0 + br)*N + bcol + bc);
        __syncthreads();
        As[ac+0][ar] = av.x; As[ac+1][ar] = av.y; As[ac+2][ar] = av.z; As[ac+3][ar] = av.w;
        *(float4*)&Bs[br][bc] = bv;
        __syncthreads();
        #pragma unroll
        for (int kk = 0; kk < 8; kk++) {
            float a[8], bb[8];
            *(float4*)&a[0]  = *(const float4*)&As[kk][ty*4];
            *(float4*)&a[4]  = *(const float4*)&As[kk][ty*4 + 64];
            *(float4*)&bb[0] = *(const float4*)&Bs[kk][tx*4];
            *(float4*)&bb[4] = *(const float4*)&Bs[kk][tx*4 + 64];
            #pragma unroll
            for (int i = 0; i < 8; i++)
                #pragma unroll
                for (int j = 0; j < 8; j++)
                    acc[i][j] += a[i]*bb[j];
        }
    }

    #pragma unroll
    for (int i = 0; i < 8; i++) {
        int row = brow + ((i < 4) ? (ty*4 + i) : (64 + ty*4 + i - 4));
        #pragma unroll
        for (int j = 0; j < 8; j++) {
            int col = bcol + ((j < 4) ? (tx*4 + j) : (64 + tx*4 + j - 4));
            float v = acc[i][j] + bias[col];
            size_t o = (size_t)row*N + col;
            if (HASADD) v += add[o];
            if (ACT)    v = v / (1.f + __expf(-v));   // silu
            if (ACCU) C[o] += v; else C[o] = v;
        }
    }
}

// ---------------- causal depthwise conv (K=4) + silu -------------------------
__global__ void conv_silu(const float* __restrict__ proj, const float* __restrict__ cw,
                          const float* __restrict__ cb, float* __restrict__ u)
{
    int idx = blockIdx.x*blockDim.x + threadIdx.x;
    if (idx >= Mrows*Ed) return;
    int e = idx % Ed;
    int m = idx / Ed;
    int l = m % Ll;
    float w0 = cw[e*4+0], w1 = cw[e*4+1], w2 = cw[e*4+2], w3 = cw[e*4+3];
    float v = cb[e];
    const float* base = proj + (size_t)m*TWO_E + e;   // proj[b][l][e] (xm half)
    if (l >= 3) v += base[-3*TWO_E]*w0;
    if (l >= 2) v += base[-2*TWO_E]*w1;
    if (l >= 1) v += base[-1*TWO_E]*w2;
    v += base[0]*w3;
    u[idx] = v / (1.f + __expf(-v));
}

// ---------------- xproj skinny GEMM: dbc[M,36] = u[M,E] @ xw[E,36] -----------
// 1 warp per row; weight k-tile staged in shared with 37-pad (conflict-free).
__global__ __launch_bounds__(256)
void xproj_kernel(const float* __restrict__ u, const float* __restrict__ xw,
                  float* __restrict__ dbc)
{
    __shared__ float sxw[128*37];
    int tid = threadIdx.x, lane = tid & 31, w = tid >> 5;
    int m = blockIdx.x*8 + w;

    float acc[DBC];
    #pragma unroll
    for (int j = 0; j < DBC; j++) acc[j] = 0.f;

    for (int k0 = 0; k0 < Ed; k0 += 128) {
        __syncthreads();
        for (int i = tid; i < 128*DBC; i += 256) {
            int k = i / DBC, j = i - k*DBC;
            sxw[k*37 + j] = xw[(size_t)k0*DBC + i];
        }
        __syncthreads();
        #pragma unroll
        for (int q = 0; q < 4; q++) {
            float uv = u[(size_t)m*Ed + k0 + q*32 + lane];
            const float* row = &sxw[(q*32 + lane)*37];
            #pragma unroll
            for (int j = 0; j < DBC; j++) acc[j] += uv * row[j];
        }
    }
    #pragma unroll
    for (int j = 0; j < DBC; j++) {
        float s = acc[j];
        s += __shfl_xor_sync(0xffffffffu, s, 16);
        s += __shfl_xor_sync(0xffffffffu, s, 8);
        s += __shfl_xor_sync(0xffffffffu, s, 4);
        s += __shfl_xor_sync(0xffffffffu, s, 2);
        s += __shfl_xor_sync(0xffffffffu, s, 1);
        if (lane == 0) dbc[(size_t)m*DBC + j] = s;
    }
}

// ---------------- selective scan (dt inline, gate inline) --------------------
// lane = one (b,e,n); 16 lanes per channel, 2 channels per warp.
__global__ void scan_kernel(const float* __restrict__ u, const float* __restrict__ dbc,
                            const float* __restrict__ proj,
                            const float* __restrict__ dt_w, const float* __restrict__ dt_b,
                            const float* __restrict__ A_log, const float* __restrict__ Dv,
                            float* __restrict__ ys)
{
    int gw = (blockIdx.x*blockDim.x + threadIdx.x) >> 5;
    int lane = threadIdx.x & 31;
    int ch = gw*2 + (lane >> 4);            // 0 .. B*E-1
    int b = ch / Ed, e = ch - b*Ed;
    int n = lane & 15;

    float Ac = -__expf(A_log[e*Nst + n]);
    float Dc = Dv[e];
    float w0 = dt_w[e], w1 = dt_w[Ed + e], w2 = dt_w[2*Ed + e], w3 = dt_w[3*Ed + e];
    float dtb = dt_b[e];

    const float* up = u    + (size_t)b*Ll*Ed + e;
    const float* dp = dbc  + (size_t)b*Ll*DBC;
    const float* gp = proj + (size_t)b*Ll*TWO_E + Ed + e;
    float*       yp = ys   + (size_t)b*Ll*Ed + e;

    float h = 0.f;
    for (int t = 0; t < Ll; t++) {
        const float* dr = dp + t*DBC;
        float xdt = dr[0]*w0 + dr[1]*w1 + dr[2]*w2 + dr[3]*w3 + dtb;
        float dtv = (xdt > 20.f) ? xdt : log1pf(__expf(xdt));
        float uv = up[(size_t)t*Ed];
        float bt = dr[Rr + n];
        float ct = dr[Rr + Nst + n];
        h = h*__expf(dtv*Ac) + (dtv*uv)*bt;
        float p = h*ct;
        p += __shfl_xor_sync(0xffffffffu, p, 8);
        p += __shfl_xor_sync(0xffffffffu, p, 4);
        p += __shfl_xor_sync(0xffffffffu, p, 2);
        p += __shfl_xor_sync(0xffffffffu, p, 1);
        if (n == 0) {
            float g = gp[(size_t)t*TWO_E];
            yp[(size_t)t*Ed] = (p + uv*Dc) / (1.f + __expf(-g));
        }
    }
}

// ---------------- hs += (0.5/C) * acc ----------------------------------------
__global__ void axpy_kernel(float* __restrict__ hs, const float* __restrict__ acc)
{
    int i = blockIdx.x*blockDim.x + threadIdx.x;
    if (i < Mrows*Hd) hs[i] += (0.5f/3.0f)*acc[i];
}

// ---------------- launch -----------------------------------------------------
extern "C" void kernel_launch(void* const* d_in, const int* in_sizes, int n_in,
                              void* d_out, int out_size)
{
    const int*   ids     = (const int*)  d_in[0];
    const float* tok_emb = (const float*)d_in[1];
    const float* pos_emb = (const float*)d_in[2];
    const float* ln_w    = (const float*)d_in[3];
    const float* ln_b    = (const float*)d_in[4];
    const float* in_w    = (const float*)d_in[5];
    const float* in_b    = (const float*)d_in[6];
    const float* conv_w  = (const float*)d_in[7];
    const float* conv_b  = (const float*)d_in[8];
    const float* xproj_w = (const float*)d_in[9];
    const float* dt_w    = (const float*)d_in[10];
    const float* dt_b    = (const float*)d_in[11];
    const float* A_log   = (const float*)d_in[12];
    const float* Dv      = (const float*)d_in[13];
    const float* out_w   = (const float*)d_in[14];
    const float* out_b   = (const float*)d_in[15];
    const float* frac_w  = (const float*)d_in[16];
    const float* frac_b  = (const float*)d_in[17];
    const float* fln_w   = (const float*)d_in[18];
    const float* fln_b   = (const float*)d_in[19];

    float *hs, *x, *proj, *u, *dbc, *ys, *acc, *yb, *yb2;
    cudaGetSymbolAddress((void**)&hs,   g_hs);
    cudaGetSymbolAddress((void**)&x,    g_x);
    cudaGetSymbolAddress((void**)&proj, g_proj);
    cudaGetSymbolAddress((void**)&u,    g_u);
    cudaGetSymbolAddress((void**)&dbc,  g_dbc);
    cudaGetSymbolAddress((void**)&ys,   g_ys);
    cudaGetSymbolAddress((void**)&acc,  g_acc);
    cudaGetSymbolAddress((void**)&yb,   g_yb);
    cudaGetSymbolAddress((void**)&yb2,  g_yb2);

    embed_kernel<<<(Mrows*Hd + 255)/256, 256>>>(ids, tok_emb, pos_emb, hs);

    for (int l = 0; l < NLY; l++) {
        ln_kernel<<<Mrows, 256>>>(hs, ln_w + (size_t)l*Hd, ln_b + (size_t)l*Hd, x);

        // proj = x @ in_w + in_b   [4096,768] x [768,3072]
        gemm128<0,0,0><<<dim3(TWO_E/128, Mrows/128), 256>>>(
            x, in_w + (size_t)l*Hd*TWO_E, in_b + (size_t)l*TWO_E, nullptr,
            proj, Mrows, Hd, TWO_E);

        conv_silu<<<(Mrows*Ed + 255)/256, 256>>>(
            proj, conv_w + (size_t)l*Ed*Kc, conv_b + (size_t)l*Ed, u);

        xproj_kernel<<<Mrows/8, 256>>>(u, xproj_w + (size_t)l*Ed*DBC, dbc);

        scan_kernel<<<192, 256>>>(u, dbc, proj,
            dt_w + (size_t)l*Rr*Ed, dt_b + (size_t)l*Ed,
            A_log + (size_t)l*Ed*Nst, Dv + (size_t)l*Ed, ys);

        // hs = ys @ out_w + out_b + hs   [4096,1536] x [1536,768]
        gemm128<0,0,1><<<dim3(Hd/128, Mrows/128), 256>>>(
            ys, out_w + (size_t)l*Ed*Hd, out_b + (size_t)l*Hd, hs,
            hs, Mrows, Ed, Hd);

        // fractal: acc = sum_i silu^3(hs)
        for (int i = 0; i < Cc; i++) {
            const float* fw = frac_w + ((size_t)l*Cc + i)*Hd*Hd;
            const float* fb = frac_b + ((size_t)l*Cc + i)*Hd;
            gemm128<1,0,0><<<dim3(Hd/128, Mrows/128), 256>>>(
                hs, fw, fb, nullptr, yb,  Mrows, Hd, Hd);
            gemm128<1,0,0><<<dim3(Hd/128, Mrows/128), 256>>>(
                yb, fw, fb, nullptr, yb2, Mrows, Hd, Hd);
            if (i == 0)
                gemm128<1,0,0><<<dim3(Hd/128, Mrows/128), 256>>>(
                    yb2, fw, fb, nullptr, acc, Mrows, Hd, Hd);
            else
                gemm128<1,1,0><<<dim3(Hd/128, Mrows/128), 256>>>(
                    yb2, fw, fb, nullptr, acc, Mrows, Hd, Hd);
        }
        axpy_kernel<<<(Mrows*Hd + 255)/256, 256>>>(hs, acc);
    }

    ln_kernel<<<Mrows, 256>>>(hs, fln_w, fln_b, (float*)d_out);
}

// round 3
// speedup vs baseline: 1.3247x; 1.3247x over previous
#include <cuda_runtime.h>
#include <cuda_bf16.h>
#include <cstdint>
#include <math.h>

#define NLY 8
#define Hd 768
#define Ed 1536
#define Nst 16
#define Rr 4
#define Kc 4
#define Cc 3
#define Bb 2
#define Ll 2048
#define Mrows (Bb*Ll)        // 4096
#define DBC (Rr+2*Nst)       // 36
#define TWO_E (2*Ed)         // 3072

// ======================= scratch (device globals) ============================
__device__ float g_hs  [Mrows*Hd];
__device__ float g_x   [Mrows*Hd];
__device__ float g_proj[Mrows*TWO_E];
__device__ float g_u   [Mrows*Ed];
__device__ float g_dbc [Mrows*DBC];
__device__ float g_ys  [Mrows*Ed];
__device__ float g_acc [Mrows*Hd];
__device__ float g_yb  [Mrows*Hd];
__device__ float g_yb2 [Mrows*Hd];

__device__ __align__(16) __nv_bfloat16 g_win_h [NLY*TWO_E*Hd];  // [3072,768]/layer
__device__ __align__(16) __nv_bfloat16 g_win_l [NLY*TWO_E*Hd];
__device__ __align__(16) __nv_bfloat16 g_wout_h[NLY*Hd*Ed];     // [768,1536]/layer
__device__ __align__(16) __nv_bfloat16 g_wout_l[NLY*Hd*Ed];
__device__ __align__(16) __nv_bfloat16 g_wfr_h [NLY*Cc*Hd*Hd];  // [768,768]/(l,i)
__device__ __align__(16) __nv_bfloat16 g_wfr_l [NLY*Cc*Hd*Hd];
__device__ __align__(16) __nv_bfloat16 g_ah [Mrows*Ed];
__device__ __align__(16) __nv_bfloat16 g_al [Mrows*Ed];
__device__ __align__(16) __nv_bfloat16 g_hsh[Mrows*Hd];
__device__ __align__(16) __nv_bfloat16 g_hsl[Mrows*Hd];

// ======================= helpers =============================================
__device__ __forceinline__ uint32_t smem_u32(const void* p) {
    uint32_t a;
    asm("{ .reg .u64 t; cvta.to.shared.u64 t, %1; cvt.u32.u64 %0, t; }" : "=r"(a) : "l"(p));
    return a;
}
__device__ __forceinline__ void cp_async16(uint32_t dst, const void* src) {
    asm volatile("cp.async.cg.shared.global [%0], [%1], 16;" :: "r"(dst), "l"(src) : "memory");
}
__device__ __forceinline__ void cp_commit() {
    asm volatile("cp.async.commit_group;" ::: "memory");
}
__device__ __forceinline__ void ldm_x4(uint32_t* r, uint32_t addr) {
    asm volatile("ldmatrix.sync.aligned.m8n8.x4.shared.b16 {%0,%1,%2,%3}, [%4];"
                 : "=r"(r[0]), "=r"(r[1]), "=r"(r[2]), "=r"(r[3]) : "r"(addr));
}
__device__ __forceinline__ void mma_bf16(float* d, const uint32_t* a, uint32_t b0, uint32_t b1) {
    asm volatile("mma.sync.aligned.m16n8k16.row.col.f32.bf16.bf16.f32 "
                 "{%0,%1,%2,%3}, {%4,%5,%6,%7}, {%8,%9}, {%0,%1,%2,%3};"
                 : "+f"(d[0]), "+f"(d[1]), "+f"(d[2]), "+f"(d[3])
                 : "r"(a[0]), "r"(a[1]), "r"(a[2]), "r"(a[3]), "r"(b0), "r"(b1));
}

// ======================= small kernels =======================================
__global__ void embed_kernel(const int* __restrict__ ids, const float* __restrict__ tok,
                             const float* __restrict__ pos, float* __restrict__ hs)
{
    int idx = blockIdx.x*blockDim.x + threadIdx.x;
    if (idx >= Mrows*Hd) return;
    int h = idx % Hd;
    int m = idx / Hd;
    int l = m % Ll;
    int id = ids[m];
    hs[idx] = tok[(size_t)id*Hd + h] + pos[(size_t)l*Hd + h];
}

__global__ void ln_kernel(const float* __restrict__ in, const float* __restrict__ w,
                          const float* __restrict__ b, float* __restrict__ out)
{
    int row = blockIdx.x;
    const float* x = in + (size_t)row*Hd;
    float s = 0.f, s2 = 0.f;
    for (int i = threadIdx.x; i < Hd; i += 256) { float v = x[i]; s += v; s2 += v*v; }
    #pragma unroll
    for (int o = 16; o; o >>= 1) {
        s  += __shfl_xor_sync(0xffffffffu, s,  o);
        s2 += __shfl_xor_sync(0xffffffffu, s2, o);
    }
    __shared__ float sa[8], sb[8];
    __shared__ float sh_mean, sh_inv;
    int wi = threadIdx.x >> 5;
    if ((threadIdx.x & 31) == 0) { sa[wi] = s; sb[wi] = s2; }
    __syncthreads();
    if (threadIdx.x == 0) {
        float ts = 0.f, t2 = 0.f;
        #pragma unroll
        for (int i = 0; i < 8; i++) { ts += sa[i]; t2 += sb[i]; }
        float m  = ts / (float)Hd;
        float var = t2 / (float)Hd - m*m;
        sh_mean = m;
        sh_inv  = rsqrtf(var + 1e-5f);
    }
    __syncthreads();
    float mean = sh_mean, inv = sh_inv;
    for (int i = threadIdx.x; i < Hd; i += 256)
        out[(size_t)row*Hd + i] = (x[i] - mean) * inv * w[i] + b[i];
}

__global__ void cvt_hilo(const float* __restrict__ x, __nv_bfloat16* __restrict__ hi,
                         __nv_bfloat16* __restrict__ lo, int n)
{
    int i = (blockIdx.x*blockDim.x + threadIdx.x) * 4;
    if (i >= n) return;
    float4 v = *(const float4*)(x + i);
    __nv_bfloat16 h[4], l[4];
    h[0] = __float2bfloat16(v.x); l[0] = __float2bfloat16(v.x - __bfloat162float(h[0]));
    h[1] = __float2bfloat16(v.y); l[1] = __float2bfloat16(v.y - __bfloat162float(h[1]));
    h[2] = __float2bfloat16(v.z); l[2] = __float2bfloat16(v.z - __bfloat162float(h[2]));
    h[3] = __float2bfloat16(v.w); l[3] = __float2bfloat16(v.w - __bfloat162float(h[3]));
    *(uint2*)(hi + i) = *(uint2*)h;
    *(uint2*)(lo + i) = *(uint2*)l;
}

// W[K,N] fp32 (batched over z) -> Wt_hi/lo [N,K] bf16
__global__ void wtrans(const float* __restrict__ W, __nv_bfloat16* __restrict__ Th,
                       __nv_bfloat16* __restrict__ Tl, int K, int N)
{
    __shared__ float t[32][33];
    size_t moff = (size_t)blockIdx.z * K * N;
    int nx = blockIdx.x*32, kx = blockIdx.y*32;
    int tx = threadIdx.x, ty = threadIdx.y;
    #pragma unroll
    for (int r = 0; r < 32; r += 8)
        t[ty + r][tx] = W[moff + (size_t)(kx + ty + r)*N + nx + tx];
    __syncthreads();
    #pragma unroll
    for (int r = 0; r < 32; r += 8) {
        float v = t[tx][ty + r];
        __nv_bfloat16 h = __float2bfloat16(v);
        size_t o = moff + (size_t)(nx + ty + r)*K + kx + tx;
        Th[o] = h;
        Tl[o] = __float2bfloat16(v - __bfloat162float(h));
    }
}

// ======================= mma.sync GEMM =======================================
// C[M,N] = act( (Ah+Al)[M,K] @ (Bh+Bl)[N,K]^T + bias [+add] )
// 128x128 CTA tile, BK=32, double-buffered cp.async; warp tile 64x32.
// smem stage: Ah(8K) Al(8K) Bh(8K) Bl(8K) = 32KB; 2 stages = 64KB.
#define GSMEM (2*4*8192)

template<int ACT, int ACCU, int HASADD>
__global__ __launch_bounds__(256, 1)
void mma_gemm(const __nv_bfloat16* __restrict__ Ah, const __nv_bfloat16* __restrict__ Al,
              const __nv_bfloat16* __restrict__ Bh, const __nv_bfloat16* __restrict__ Bl,
              const float* __restrict__ bias, const float* __restrict__ add,
              float* __restrict__ C, int M, int K, int N)
{
    extern __shared__ __align__(16) char smem[];
    const uint32_t sb0 = smem_u32(smem);
    int tid = threadIdx.x, lane = tid & 31, wid = tid >> 5;
    int m0 = blockIdx.y << 7, n0 = blockIdx.x << 7;
    int wm = (wid >> 2) * 64, wn = (wid & 3) * 32;

    const __nv_bfloat16* gsrc[4] = {
        Ah + (size_t)m0*K, Al + (size_t)m0*K,
        Bh + (size_t)n0*K, Bl + (size_t)n0*K };

    // per-thread copy slots: idx = tid*2+q -> (row=idx>>2, chunk=idx&3)
    const int r0 = (tid*2) >> 2, c0 = (tid*2) & 3;
    const int r1 = (tid*2+1) >> 2, c1 = (tid*2+1) & 3;
    const uint32_t so0 = (uint32_t)(r0*64 + ((c0 ^ ((r0>>1)&3))<<4));
    const uint32_t so1 = (uint32_t)(r1*64 + ((c1 ^ ((r1>>1)&3))<<4));

    float acc[4][4][4];
    #pragma unroll
    for (int t = 0; t < 4; t++)
        #pragma unroll
        for (int j = 0; j < 4; j++)
            #pragma unroll
            for (int e = 0; e < 4; e++) acc[t][j][e] = 0.f;

    const int nt = K >> 5;

    // prefetch tile 0
    {
        #pragma unroll
        for (int mat = 0; mat < 4; mat++) {
            const char* src = (const char*)gsrc[mat];
            uint32_t sbase = sb0 + mat*8192u;
            cp_async16(sbase + so0, src + (size_t)r0*K*2 + c0*16);
            cp_async16(sbase + so1, src + (size_t)r1*K*2 + c1*16);
        }
        cp_commit();
    }

    for (int i = 0; i < nt; i++) {
        if (i + 1 < nt) {
            int k0 = (i + 1) << 5;
            uint32_t st = sb0 + ((i + 1) & 1)*32768u;
            #pragma unroll
            for (int mat = 0; mat < 4; mat++) {
                const char* src = (const char*)(gsrc[mat] + k0);
                uint32_t sbase = st + mat*8192u;
                cp_async16(sbase + so0, src + (size_t)r0*K*2 + c0*16);
                cp_async16(sbase + so1, src + (size_t)r1*K*2 + c1*16);
            }
            cp_commit();
            asm volatile("cp.async.wait_group 1;" ::: "memory");
        } else {
            asm volatile("cp.async.wait_group 0;" ::: "memory");
        }
        __syncthreads();

        uint32_t st = sb0 + (i & 1)*32768u;
        int g = lane >> 3;
        int rA = (lane & 7) + (g & 1)*8;       // row-in-16-tile
        int kh = g >> 1;                        // k-half (8)

        #pragma unroll
        for (int s = 0; s < 2; s++) {
            int cch = s*2 + kh;
            uint32_t ah[4][4], al_[4][4], bh[2][4], bl[2][4];
            #pragma unroll
            for (int t = 0; t < 4; t++) {
                int row = wm + t*16 + rA;
                uint32_t off = (uint32_t)(row*64 + ((cch ^ ((row>>1)&3))<<4));
                ldm_x4(ah[t],  st + off);
                ldm_x4(al_[t], st + 8192u + off);
            }
            #pragma unroll
            for (int u = 0; u < 2; u++) {
                int row = wn + u*16 + rA;
                uint32_t off = (uint32_t)(row*64 + ((cch ^ ((row>>1)&3))<<4));
                ldm_x4(bh[u], st + 16384u + off);
                ldm_x4(bl[u], st + 24576u + off);
            }
            #pragma unroll
            for (int t = 0; t < 4; t++)
                #pragma unroll
                for (int j = 0; j < 4; j++) {
                    int u = j >> 1, w = j & 1;
                    mma_bf16(acc[t][j], ah[t],  bh[u][w], bh[u][w+2]);
                    mma_bf16(acc[t][j], ah[t],  bl[u][w], bl[u][w+2]);
                    mma_bf16(acc[t][j], al_[t], bh[u][w], bh[u][w+2]);
                }
        }
        __syncthreads();
    }

    // ---- epilogue from register accumulators ----
    #pragma unroll
    for (int t = 0; t < 4; t++) {
        int mrow = m0 + wm + t*16 + (lane >> 2);
        #pragma unroll
        for (int j = 0; j < 4; j++) {
            int col = n0 + wn + j*8 + 2*(lane & 3);
            float b0 = bias[col], b1 = bias[col+1];
            #pragma unroll
            for (int half = 0; half < 2; half++) {
                int row = mrow + half*8;
                float v0 = acc[t][j][half*2+0] + b0;
                float v1 = acc[t][j][half*2+1] + b1;
                size_t o = (size_t)row*N + col;
                if (HASADD) { v0 += add[o]; v1 += add[o+1]; }
                if (ACT) {
                    v0 = v0 / (1.f + __expf(-v0));
                    v1 = v1 / (1.f + __expf(-v1));
                }
                if (ACCU) { v0 += C[o]; v1 += C[o+1]; }
                *(float2*)(C + o) = make_float2(v0, v1);
            }
        }
    }
}

// ======================= conv / xproj / scan / axpy ==========================
__global__ void conv_silu(const float* __restrict__ proj, const float* __restrict__ cw,
                          const float* __restrict__ cb, float* __restrict__ u)
{
    int idx = blockIdx.x*blockDim.x + threadIdx.x;
    if (idx >= Mrows*Ed) return;
    int e = idx % Ed;
    int m = idx / Ed;
    int l = m % Ll;
    float w0 = cw[e*4+0], w1 = cw[e*4+1], w2 = cw[e*4+2], w3 = cw[e*4+3];
    float v = cb[e];
    const float* base = proj + (size_t)m*TWO_E + e;
    if (l >= 3) v += base[-3*TWO_E]*w0;
    if (l >= 2) v += base[-2*TWO_E]*w1;
    if (l >= 1) v += base[-1*TWO_E]*w2;
    v += base[0]*w3;
    u[idx] = v / (1.f + __expf(-v));
}

__global__ __launch_bounds__(256)
void xproj_kernel(const float* __restrict__ u, const float* __restrict__ xw,
                  float* __restrict__ dbc)
{
    __shared__ float sxw[128*37];
    int tid = threadIdx.x, lane = tid & 31, w = tid >> 5;
    int m = blockIdx.x*8 + w;

    float acc[DBC];
    #pragma unroll
    for (int j = 0; j < DBC; j++) acc[j] = 0.f;

    for (int k0 = 0; k0 < Ed; k0 += 128) {
        __syncthreads();
        for (int i = tid; i < 128*DBC; i += 256) {
            int k = i / DBC, j = i - k*DBC;
            sxw[k*37 + j] = xw[(size_t)k0*DBC + i];
        }
        __syncthreads();
        #pragma unroll
        for (int q = 0; q < 4; q++) {
            float uv = u[(size_t)m*Ed + k0 + q*32 + lane];
            const float* row = &sxw[(q*32 + lane)*37];
            #pragma unroll
            for (int j = 0; j < DBC; j++) acc[j] += uv * row[j];
        }
    }
    #pragma unroll
    for (int j = 0; j < DBC; j++) {
        float s = acc[j];
        s += __shfl_xor_sync(0xffffffffu, s, 16);
        s += __shfl_xor_sync(0xffffffffu, s, 8);
        s += __shfl_xor_sync(0xffffffffu, s, 4);
        s += __shfl_xor_sync(0xffffffffu, s, 2);
        s += __shfl_xor_sync(0xffffffffu, s, 1);
        if (lane == 0) dbc[(size_t)m*DBC + j] = s;
    }
}

__global__ void scan_kernel(const float* __restrict__ u, const float* __restrict__ dbc,
                            const float* __restrict__ proj,
                            const float* __restrict__ dt_w, const float* __restrict__ dt_b,
                            const float* __restrict__ A_log, const float* __restrict__ Dv,
                            float* __restrict__ ys)
{
    int gw = (blockIdx.x*blockDim.x + threadIdx.x) >> 5;
    int lane = threadIdx.x & 31;
    int ch = gw*2 + (lane >> 4);
    int b = ch / Ed, e = ch - b*Ed;
    int n = lane & 15;

    float Ac = -__expf(A_log[e*Nst + n]);
    float Dc = Dv[e];
    float w0 = dt_w[e], w1 = dt_w[Ed + e], w2 = dt_w[2*Ed + e], w3 = dt_w[3*Ed + e];
    float dtb = dt_b[e];

    const float* up = u    + (size_t)b*Ll*Ed + e;
    const float* dp = dbc  + (size_t)b*Ll*DBC;
    const float* gp = proj + (size_t)b*Ll*TWO_E + Ed + e;
    float*       yp = ys   + (size_t)b*Ll*Ed + e;

    float h = 0.f;
    for (int t = 0; t < Ll; t++) {
        const float* dr = dp + t*DBC;
        float xdt = dr[0]*w0 + dr[1]*w1 + dr[2]*w2 + dr[3]*w3 + dtb;
        float dtv = (xdt > 20.f) ? xdt : log1pf(__expf(xdt));
        float uv = up[(size_t)t*Ed];
        float bt = dr[Rr + n];
        float ct = dr[Rr + Nst + n];
        h = h*__expf(dtv*Ac) + (dtv*uv)*bt;
        float p = h*ct;
        p += __shfl_xor_sync(0xffffffffu, p, 8);
        p += __shfl_xor_sync(0xffffffffu, p, 4);
        p += __shfl_xor_sync(0xffffffffu, p, 2);
        p += __shfl_xor_sync(0xffffffffu, p, 1);
        if (n == 0) {
            float g = gp[(size_t)t*TWO_E];
            yp[(size_t)t*Ed] = (p + uv*Dc) / (1.f + __expf(-g));
        }
    }
}

__global__ void axpy_kernel(float* __restrict__ hs, const float* __restrict__ acc)
{
    int i = blockIdx.x*blockDim.x + threadIdx.x;
    if (i < Mrows*Hd) hs[i] += (0.5f/3.0f)*acc[i];
}

// ======================= launch ==============================================
extern "C" void kernel_launch(void* const* d_in, const int* in_sizes, int n_in,
                              void* d_out, int out_size)
{
    const int*   ids     = (const int*)  d_in[0];
    const float* tok_emb = (const float*)d_in[1];
    const float* pos_emb = (const float*)d_in[2];
    const float* ln_w    = (const float*)d_in[3];
    const float* ln_b    = (const float*)d_in[4];
    const float* in_w    = (const float*)d_in[5];
    const float* in_b    = (const float*)d_in[6];
    const float* conv_w  = (const float*)d_in[7];
    const float* conv_b  = (const float*)d_in[8];
    const float* xproj_w = (const float*)d_in[9];
    const float* dt_w    = (const float*)d_in[10];
    const float* dt_b    = (const float*)d_in[11];
    const float* A_log   = (const float*)d_in[12];
    const float* Dv      = (const float*)d_in[13];
    const float* out_w   = (const float*)d_in[14];
    const float* out_b   = (const float*)d_in[15];
    const float* frac_w  = (const float*)d_in[16];
    const float* frac_b  = (const float*)d_in[17];
    const float* fln_w   = (const float*)d_in[18];
    const float* fln_b   = (const float*)d_in[19];

    float *hs, *x, *proj, *u, *dbc, *ys, *acc, *yb, *yb2;
    __nv_bfloat16 *winh, *winl, *wouth, *woutl, *wfrh, *wfrl, *ah, *al, *hsh, *hsl;
    cudaGetSymbolAddress((void**)&hs,   g_hs);
    cudaGetSymbolAddress((void**)&x,    g_x);
    cudaGetSymbolAddress((void**)&proj, g_proj);
    cudaGetSymbolAddress((void**)&u,    g_u);
    cudaGetSymbolAddress((void**)&dbc,  g_dbc);
    cudaGetSymbolAddress((void**)&ys,   g_ys);
    cudaGetSymbolAddress((void**)&acc,  g_acc);
    cudaGetSymbolAddress((void**)&yb,   g_yb);
    cudaGetSymbolAddress((void**)&yb2,  g_yb2);
    cudaGetSymbolAddress((void**)&winh,  g_win_h);
    cudaGetSymbolAddress((void**)&winl,  g_win_l);
    cudaGetSymbolAddress((void**)&wouth, g_wout_h);
    cudaGetSymbolAddress((void**)&woutl, g_wout_l);
    cudaGetSymbolAddress((void**)&wfrh,  g_wfr_h);
    cudaGetSymbolAddress((void**)&wfrl,  g_wfr_l);
    cudaGetSymbolAddress((void**)&ah,   g_ah);
    cudaGetSymbolAddress((void**)&al,   g_al);
    cudaGetSymbolAddress((void**)&hsh,  g_hsh);
    cudaGetSymbolAddress((void**)&hsl,  g_hsl);

    cudaFuncSetAttribute(mma_gemm<0,0,0>, cudaFuncAttributeMaxDynamicSharedMemorySize, GSMEM);
    cudaFuncSetAttribute(mma_gemm<0,0,1>, cudaFuncAttributeMaxDynamicSharedMemorySize, GSMEM);
    cudaFuncSetAttribute(mma_gemm<1,0,0>, cudaFuncAttributeMaxDynamicSharedMemorySize, GSMEM);
    cudaFuncSetAttribute(mma_gemm<1,1,0>, cudaFuncAttributeMaxDynamicSharedMemorySize, GSMEM);

    // weight transpose + hi/lo split (all layers, once per launch)
    wtrans<<<dim3(TWO_E/32, Hd/32, NLY), dim3(32,8)>>>(in_w, winh, winl, Hd, TWO_E);
    wtrans<<<dim3(Hd/32, Ed/32, NLY),    dim3(32,8)>>>(out_w, wouth, woutl, Ed, Hd);
    wtrans<<<dim3(Hd/32, Hd/32, NLY*Cc), dim3(32,8)>>>(frac_w, wfrh, wfrl, Hd, Hd);

    embed_kernel<<<(Mrows*Hd + 255)/256, 256>>>(ids, tok_emb, pos_emb, hs);

    for (int l = 0; l < NLY; l++) {
        ln_kernel<<<Mrows, 256>>>(hs, ln_w + (size_t)l*Hd, ln_b + (size_t)l*Hd, x);

        // proj = x @ in_w + in_b
        cvt_hilo<<<(Mrows*Hd/4 + 255)/256, 256>>>(x, ah, al, Mrows*Hd);
        mma_gemm<0,0,0><<<dim3(TWO_E/128, Mrows/128), 256, GSMEM>>>(
            ah, al, winh + (size_t)l*TWO_E*Hd, winl + (size_t)l*TWO_E*Hd,
            in_b + (size_t)l*TWO_E, nullptr, proj, Mrows, Hd, TWO_E);

        conv_silu<<<(Mrows*Ed + 255)/256, 256>>>(
            proj, conv_w + (size_t)l*Ed*Kc, conv_b + (size_t)l*Ed, u);

        xproj_kernel<<<Mrows/8, 256>>>(u, xproj_w + (size_t)l*Ed*DBC, dbc);

        scan_kernel<<<192, 256>>>(u, dbc, proj,
            dt_w + (size_t)l*Rr*Ed, dt_b + (size_t)l*Ed,
            A_log + (size_t)l*Ed*Nst, Dv + (size_t)l*Ed, ys);

        // hs = ys @ out_w + out_b + hs
        cvt_hilo<<<(Mrows*Ed/4 + 255)/256, 256>>>(ys, ah, al, Mrows*Ed);
        mma_gemm<0,0,1><<<dim3(Hd/128, Mrows/128), 256, GSMEM>>>(
            ah, al, wouth + (size_t)l*Hd*Ed, woutl + (size_t)l*Hd*Ed,
            out_b + (size_t)l*Hd, hs, hs, Mrows, Ed, Hd);

        // fractal
        cvt_hilo<<<(Mrows*Hd/4 + 255)/256, 256>>>(hs, hsh, hsl, Mrows*Hd);
        for (int i = 0; i < Cc; i++) {
            const __nv_bfloat16* fwh = wfrh + ((size_t)l*Cc + i)*Hd*Hd;
            const __nv_bfloat16* fwl = wfrl + ((size_t)l*Cc + i)*Hd*Hd;
            const float* fb = frac_b + ((size_t)l*Cc + i)*Hd;
            mma_gemm<1,0,0><<<dim3(Hd/128, Mrows/128), 256, GSMEM>>>(
                hsh, hsl, fwh, fwl, fb, nullptr, yb, Mrows, Hd, Hd);
            cvt_hilo<<<(Mrows*Hd/4 + 255)/256, 256>>>(yb, ah, al, Mrows*Hd);
            mma_gemm<1,0,0><<<dim3(Hd/128, Mrows/128), 256, GSMEM>>>(
                ah, al, fwh, fwl, fb, nullptr, yb2, Mrows, Hd, Hd);
            cvt_hilo<<<(Mrows*Hd/4 + 255)/256, 256>>>(yb2, ah, al, Mrows*Hd);
            if (i == 0)
                mma_gemm<1,0,0><<<dim3(Hd/128, Mrows/128), 256, GSMEM>>>(
                    ah, al, fwh, fwl, fb, nullptr, acc, Mrows, Hd, Hd);
            else
                mma_gemm<1,1,0><<<dim3(Hd/128, Mrows/128), 256, GSMEM>>>(
                    ah, al, fwh, fwl, fb, nullptr, acc, Mrows, Hd, Hd);
        }
        axpy_kernel<<<(Mrows*Hd + 255)/256, 256>>>(hs, acc);
    }

    ln_kernel<<<Mrows, 256>>>(hs, fln_w, fln_b, (float*)d_out);
}

// round 4
// speedup vs baseline: 1.3953x; 1.0533x over previous
#include <cuda_runtime.h>
#include <cuda_bf16.h>
#include <cstdint>
#include <math.h>

#define NLY 8
#define Hd 768
#define Ed 1536
#define Nst 16
#define Rr 4
#define Kc 4
#define Cc 3
#define Bb 2
#define Ll 2048
#define Mrows (Bb*Ll)        // 4096
#define DBC (Rr+2*Nst)       // 36
#define TWO_E (2*Ed)         // 3072

// ======================= scratch (device globals) ============================
__device__ float g_hs  [Mrows*Hd];
__device__ float g_proj[Mrows*TWO_E];
__device__ float g_u   [Mrows*Ed];
__device__ float g_dbc [Mrows*DBC];
__device__ float g_acc [Mrows*Hd];

__device__ __align__(16) __nv_bfloat16 g_win_h [NLY*TWO_E*Hd];
__device__ __align__(16) __nv_bfloat16 g_win_l [NLY*TWO_E*Hd];
__device__ __align__(16) __nv_bfloat16 g_wout_h[NLY*Hd*Ed];
__device__ __align__(16) __nv_bfloat16 g_wout_l[NLY*Hd*Ed];
__device__ __align__(16) __nv_bfloat16 g_wfr_h [NLY*Cc*Hd*Hd];
__device__ __align__(16) __nv_bfloat16 g_wfr_l [NLY*Cc*Hd*Hd];
__device__ __align__(16) __nv_bfloat16 g_ah [Mrows*Ed];   // x | ys | yb   (hi)
__device__ __align__(16) __nv_bfloat16 g_al [Mrows*Ed];   //               (lo)
__device__ __align__(16) __nv_bfloat16 g_hsh[Mrows*Hd];
__device__ __align__(16) __nv_bfloat16 g_hsl[Mrows*Hd];
__device__ __align__(16) __nv_bfloat16 g_ybh[Mrows*Hd];
__device__ __align__(16) __nv_bfloat16 g_ybl[Mrows*Hd];

// ======================= helpers =============================================
__device__ __forceinline__ uint32_t smem_u32(const void* p) {
    uint32_t a;
    asm("{ .reg .u64 t; cvta.to.shared.u64 t, %1; cvt.u32.u64 %0, t; }" : "=r"(a) : "l"(p));
    return a;
}
__device__ __forceinline__ void cp_async16(uint32_t dst, const void* src) {
    asm volatile("cp.async.cg.shared.global [%0], [%1], 16;" :: "r"(dst), "l"(src) : "memory");
}
__device__ __forceinline__ void cp_commit() {
    asm volatile("cp.async.commit_group;" ::: "memory");
}
__device__ __forceinline__ void ldm_x4(uint32_t* r, uint32_t addr) {
    asm volatile("ldmatrix.sync.aligned.m8n8.x4.shared.b16 {%0,%1,%2,%3}, [%4];"
                 : "=r"(r[0]), "=r"(r[1]), "=r"(r[2]), "=r"(r[3]) : "r"(addr));
}
__device__ __forceinline__ void mma_bf16(float* d, const uint32_t* a, uint32_t b0, uint32_t b1) {
    asm volatile("mma.sync.aligned.m16n8k16.row.col.f32.bf16.bf16.f32 "
                 "{%0,%1,%2,%3}, {%4,%5,%6,%7}, {%8,%9}, {%0,%1,%2,%3};"
                 : "+f"(d[0]), "+f"(d[1]), "+f"(d[2]), "+f"(d[3])
                 : "r"(a[0]), "r"(a[1]), "r"(a[2]), "r"(a[3]), "r"(b0), "r"(b1));
}

// ======================= small kernels =======================================
__global__ void embed_kernel(const int* __restrict__ ids, const float* __restrict__ tok,
                             const float* __restrict__ pos, float* __restrict__ hs)
{
    int idx = blockIdx.x*blockDim.x + threadIdx.x;
    if (idx >= Mrows*Hd) return;
    int h = idx % Hd;
    int m = idx / Hd;
    int l = m % Ll;
    int id = ids[m];
    hs[idx] = tok[(size_t)id*Hd + h] + pos[(size_t)l*Hd + h];
}

// LayerNorm, optionally fused with  hs += (1/6)*acc  (previous layer's fractal),
// output either fp32 or bf16 hi/lo.
template<int HASACC, int OUTHILO>
__global__ void ln_fused(float* __restrict__ hs, const float* __restrict__ accv,
                         const float* __restrict__ w, const float* __restrict__ b,
                         float* __restrict__ out32,
                         __nv_bfloat16* __restrict__ oh, __nv_bfloat16* __restrict__ ol)
{
    int row = blockIdx.x;
    size_t base = (size_t)row*Hd;
    int tid = threadIdx.x;
    float v[3];
    float s = 0.f, s2 = 0.f;
    #pragma unroll
    for (int q = 0; q < 3; q++) {
        int i = tid + q*256;
        float t = hs[base + i];
        if (HASACC) { t += (0.5f/3.0f)*accv[base + i]; hs[base + i] = t; }
        v[q] = t;
        s += t; s2 += t*t;
    }
    #pragma unroll
    for (int o = 16; o; o >>= 1) {
        s  += __shfl_xor_sync(0xffffffffu, s,  o);
        s2 += __shfl_xor_sync(0xffffffffu, s2, o);
    }
    __shared__ float sa[8], sb[8];
    __shared__ float sh_mean, sh_inv;
    int wi = tid >> 5;
    if ((tid & 31) == 0) { sa[wi] = s; sb[wi] = s2; }
    __syncthreads();
    if (tid == 0) {
        float ts = 0.f, t2 = 0.f;
        #pragma unroll
        for (int i = 0; i < 8; i++) { ts += sa[i]; t2 += sb[i]; }
        float m  = ts / (float)Hd;
        float var = t2 / (float)Hd - m*m;
        sh_mean = m;
        sh_inv  = rsqrtf(var + 1e-5f);
    }
    __syncthreads();
    float mean = sh_mean, inv = sh_inv;
    #pragma unroll
    for (int q = 0; q < 3; q++) {
        int i = tid + q*256;
        float y = (v[q] - mean) * inv * w[i] + b[i];
        if (OUTHILO) {
            __nv_bfloat16 h = __float2bfloat16(y);
            oh[base + i] = h;
            ol[base + i] = __float2bfloat16(y - __bfloat162float(h));
        } else {
            out32[base + i] = y;
        }
    }
}

// W[K,N] fp32 (batched over z) -> Wt_hi/lo [N,K] bf16
__global__ void wtrans(const float* __restrict__ W, __nv_bfloat16* __restrict__ Th,
                       __nv_bfloat16* __restrict__ Tl, int K, int N)
{
    __shared__ float t[32][33];
    size_t moff = (size_t)blockIdx.z * K * N;
    int nx = blockIdx.x*32, kx = blockIdx.y*32;
    int tx = threadIdx.x, ty = threadIdx.y;
    #pragma unroll
    for (int r = 0; r < 32; r += 8)
        t[ty + r][tx] = W[moff + (size_t)(kx + ty + r)*N + nx + tx];
    __syncthreads();
    #pragma unroll
    for (int r = 0; r < 32; r += 8) {
        float v = t[tx][ty + r];
        __nv_bfloat16 h = __float2bfloat16(v);
        size_t o = moff + (size_t)(nx + ty + r)*K + kx + tx;
        Th[o] = h;
        Tl[o] = __float2bfloat16(v - __bfloat162float(h));
    }
}

// ======================= mma.sync GEMM =======================================
// C = act( (Ah+Al)[M,K] @ (Bh+Bl)[N,K]^T + bias [+add] )
// 128x128 CTA tile, BK=32, 3-stage cp.async pipeline, 2 CTAs/SM.
#define GSTAGE 32768
#define GSMEM  (3*GSTAGE)

template<int ACT, int ACCU, int HASADD, int OUTF32, int OUTHILO>
__global__ __launch_bounds__(256, 2)
void mma_gemm(const __nv_bfloat16* __restrict__ Ah, const __nv_bfloat16* __restrict__ Al,
              const __nv_bfloat16* __restrict__ Bh, const __nv_bfloat16* __restrict__ Bl,
              const float* __restrict__ bias, const float* __restrict__ add,
              float* __restrict__ C, __nv_bfloat16* __restrict__ Oh,
              __nv_bfloat16* __restrict__ Ol, int M, int K, int N)
{
    extern __shared__ __align__(16) char smem[];
    const uint32_t sb0 = smem_u32(smem);
    int tid = threadIdx.x, lane = tid & 31, wid = tid >> 5;
    int m0 = blockIdx.y << 7, n0 = blockIdx.x << 7;
    int wm = (wid >> 2) * 64, wn = (wid & 3) * 32;

    const __nv_bfloat16* gsrc[4] = {
        Ah + (size_t)m0*K, Al + (size_t)m0*K,
        Bh + (size_t)n0*K, Bl + (size_t)n0*K };

    const int r0 = (tid*2) >> 2, c0 = (tid*2) & 3;
    const int r1 = (tid*2+1) >> 2, c1 = (tid*2+1) & 3;
    const uint32_t so0 = (uint32_t)(r0*64 + ((c0 ^ ((r0>>1)&3))<<4));
    const uint32_t so1 = (uint32_t)(r1*64 + ((c1 ^ ((r1>>1)&3))<<4));

    float acc[4][4][4];
    #pragma unroll
    for (int t = 0; t < 4; t++)
        #pragma unroll
        for (int j = 0; j < 4; j++)
            #pragma unroll
            for (int e = 0; e < 4; e++) acc[t][j][e] = 0.f;

    const int nt = K >> 5;

    // prefetch stages 0, 1
    #pragma unroll
    for (int p = 0; p < 2; p++) {
        uint32_t st = sb0 + p*GSTAGE;
        int k0 = p << 5;
        #pragma unroll
        for (int mat = 0; mat < 4; mat++) {
            const char* src = (const char*)(gsrc[mat] + k0);
            uint32_t sbase = st + mat*8192u;
            cp_async16(sbase + so0, src + (size_t)r0*K*2 + c0*16);
            cp_async16(sbase + so1, src + (size_t)r1*K*2 + c1*16);
        }
        cp_commit();
    }

    int stage = 0, pstage = 2;
    for (int i = 0; i < nt; i++) {
        if (i == nt - 1) asm volatile("cp.async.wait_group 0;" ::: "memory");
        else             asm volatile("cp.async.wait_group 1;" ::: "memory");
        __syncthreads();

        uint32_t st = sb0 + stage*GSTAGE;
        int g = lane >> 3;
        int rA = (lane & 7) + (g & 1)*8;
        int kh = g >> 1;

        #pragma unroll
        for (int s = 0; s < 2; s++) {
            int cch = s*2 + kh;
            uint32_t bh[2][4], bl[2][4];
            #pragma unroll
            for (int u = 0; u < 2; u++) {
                int row = wn + u*16 + rA;
                uint32_t off = (uint32_t)(row*64 + ((cch ^ ((row>>1)&3))<<4));
                ldm_x4(bh[u], st + 16384u + off);
                ldm_x4(bl[u], st + 24576u + off);
            }
            #pragma unroll
            for (int t = 0; t < 4; t++) {
                int row = wm + t*16 + rA;
                uint32_t off = (uint32_t)(row*64 + ((cch ^ ((row>>1)&3))<<4));
                uint32_t ah4[4], al4[4];
                ldm_x4(ah4, st + off);
                ldm_x4(al4, st + 8192u + off);
                #pragma unroll
                for (int j = 0; j < 4; j++) {
                    int u = j >> 1, w = j & 1;
                    mma_bf16(acc[t][j], ah4, bh[u][w], bh[u][w+2]);
                    mma_bf16(acc[t][j], ah4, bl[u][w], bl[u][w+2]);
                    mma_bf16(acc[t][j], al4, bh[u][w], bh[u][w+2]);
                }
            }
        }

        if (i + 2 < nt) {
            uint32_t stp = sb0 + pstage*GSTAGE;
            int k0 = (i + 2) << 5;
            #pragma unroll
            for (int mat = 0; mat < 4; mat++) {
                const char* src = (const char*)(gsrc[mat] + k0);
                uint32_t sbase = stp + mat*8192u;
                cp_async16(sbase + so0, src + (size_t)r0*K*2 + c0*16);
                cp_async16(sbase + so1, src + (size_t)r1*K*2 + c1*16);
            }
            cp_commit();
        }
        stage = (stage + 1 == 3) ? 0 : stage + 1;
        pstage = (pstage + 1 == 3) ? 0 : pstage + 1;
    }

    // ---- epilogue ----
    #pragma unroll
    for (int t = 0; t < 4; t++) {
        int mrow = m0 + wm + t*16 + (lane >> 2);
        #pragma unroll
        for (int j = 0; j < 4; j++) {
            int col = n0 + wn + j*8 + 2*(lane & 3);
            float b0 = bias[col], b1 = bias[col+1];
            #pragma unroll
            for (int half = 0; half < 2; half++) {
                int row = mrow + half*8;
                float v0 = acc[t][j][half*2+0] + b0;
                float v1 = acc[t][j][half*2+1] + b1;
                size_t o = (size_t)row*N + col;
                if (HASADD) { v0 += add[o]; v1 += add[o+1]; }
                if (ACT) {
                    v0 = v0 / (1.f + __expf(-v0));
                    v1 = v1 / (1.f + __expf(-v1));
                }
                if (OUTF32) {
                    if (ACCU) { v0 += C[o]; v1 += C[o+1]; }
                    *(float2*)(C + o) = make_float2(v0, v1);
                }
                if (OUTHILO) {
                    __nv_bfloat16 h0 = __float2bfloat16(v0);
                    __nv_bfloat16 h1 = __float2bfloat16(v1);
                    __nv_bfloat162 hh; hh.x = h0; hh.y = h1;
                    __nv_bfloat162 ll;
                    ll.x = __float2bfloat16(v0 - __bfloat162float(h0));
                    ll.y = __float2bfloat16(v1 - __bfloat162float(h1));
                    *(__nv_bfloat162*)(Oh + o) = hh;
                    *(__nv_bfloat162*)(Ol + o) = ll;
                }
            }
        }
    }
}

// ======================= conv / xproj / scan =================================
__global__ void conv_silu(const float* __restrict__ proj, const float* __restrict__ cw,
                          const float* __restrict__ cb, float* __restrict__ u)
{
    int idx = blockIdx.x*blockDim.x + threadIdx.x;
    if (idx >= Mrows*Ed) return;
    int e = idx % Ed;
    int m = idx / Ed;
    int l = m % Ll;
    float w0 = cw[e*4+0], w1 = cw[e*4+1], w2 = cw[e*4+2], w3 = cw[e*4+3];
    float v = cb[e];
    const float* base = proj + (size_t)m*TWO_E + e;
    if (l >= 3) v += base[-3*TWO_E]*w0;
    if (l >= 2) v += base[-2*TWO_E]*w1;
    if (l >= 1) v += base[-1*TWO_E]*w2;
    v += base[0]*w3;
    u[idx] = v / (1.f + __expf(-v));
}

__global__ __launch_bounds__(256)
void xproj_kernel(const float* __restrict__ u, const float* __restrict__ xw,
                  float* __restrict__ dbc)
{
    __shared__ float sxw[128*37];
    int tid = threadIdx.x, lane = tid & 31, w = tid >> 5;
    int m = blockIdx.x*8 + w;

    float acc[DBC];
    #pragma unroll
    for (int j = 0; j < DBC; j++) acc[j] = 0.f;

    for (int k0 = 0; k0 < Ed; k0 += 128) {
        __syncthreads();
        for (int i = tid; i < 128*DBC; i += 256) {
            int k = i / DBC, j = i - k*DBC;
            sxw[k*37 + j] = xw[(size_t)k0*DBC + i];
        }
        __syncthreads();
        #pragma unroll
        for (int q = 0; q < 4; q++) {
            float uv = u[(size_t)m*Ed + k0 + q*32 + lane];
            const float* row = &sxw[(q*32 + lane)*37];
            #pragma unroll
            for (int j = 0; j < DBC; j++) acc[j] += uv * row[j];
        }
    }
    #pragma unroll
    for (int j = 0; j < DBC; j++) {
        float s = acc[j];
        s += __shfl_xor_sync(0xffffffffu, s, 16);
        s += __shfl_xor_sync(0xffffffffu, s, 8);
        s += __shfl_xor_sync(0xffffffffu, s, 4);
        s += __shfl_xor_sync(0xffffffffu, s, 2);
        s += __shfl_xor_sync(0xffffffffu, s, 1);
        if (lane == 0) dbc[(size_t)m*DBC + j] = s;
    }
}

// Selective scan; 4 timesteps per reduction round; ys emitted as bf16 hi/lo.
__global__ void scan_kernel(const float* __restrict__ u, const float* __restrict__ dbc,
                            const float* __restrict__ proj,
                            const float* __restrict__ dt_w, const float* __restrict__ dt_b,
                            const float* __restrict__ A_log, const float* __restrict__ Dv,
                            __nv_bfloat16* __restrict__ ysh, __nv_bfloat16* __restrict__ ysl)
{
    int gw = (blockIdx.x*blockDim.x + threadIdx.x) >> 5;
    int lane = threadIdx.x & 31;
    int ch = gw*2 + (lane >> 4);
    int b = ch / Ed, e = ch - b*Ed;
    int n = lane & 15;

    float Ac = -__expf(A_log[e*Nst + n]);
    float Dc = Dv[e];
    float w0 = dt_w[e], w1 = dt_w[Ed + e], w2 = dt_w[2*Ed + e], w3 = dt_w[3*Ed + e];
    float dtb = dt_b[e];

    const float* up = u    + (size_t)b*Ll*Ed + e;
    const float* dp = dbc  + (size_t)b*Ll*DBC;
    const float* gp = proj + (size_t)b*Ll*TWO_E + Ed + e;
    size_t ybase = (size_t)b*Ll*Ed + e;

    float h = 0.f;
    for (int t0 = 0; t0 < Ll; t0 += 4) {
        float p[4], uq[4];
        #pragma unroll
        for (int q = 0; q < 4; q++) {
            int t = t0 + q;
            const float* dr = dp + t*DBC;
            float4 d4 = *(const float4*)dr;
            float xdt = d4.x*w0 + d4.y*w1 + d4.z*w2 + d4.w*w3 + dtb;
            float dtv = (xdt > 20.f) ? xdt : log1pf(__expf(xdt));
            float uv = up[(size_t)t*Ed];
            float bt = dr[Rr + n];
            float ct = dr[Rr + Nst + n];
            h = h*__expf(dtv*Ac) + (dtv*uv)*bt;
            p[q] = h*ct;
            uq[q] = uv;
        }
        #pragma unroll
        for (int q = 0; q < 4; q++) {
            p[q] += __shfl_xor_sync(0xffffffffu, p[q], 8);
            p[q] += __shfl_xor_sync(0xffffffffu, p[q], 4);
            p[q] += __shfl_xor_sync(0xffffffffu, p[q], 2);
            p[q] += __shfl_xor_sync(0xffffffffu, p[q], 1);
        }
        if (n == 0) {
            #pragma unroll
            for (int q = 0; q < 4; q++) {
                int t = t0 + q;
                float g = gp[(size_t)t*TWO_E];
                float y = (p[q] + uq[q]*Dc) / (1.f + __expf(-g));
                __nv_bfloat16 hh = __float2bfloat16(y);
                ysh[ybase + (size_t)t*Ed] = hh;
                ysl[ybase + (size_t)t*Ed] = __float2bfloat16(y - __bfloat162float(hh));
            }
        }
    }
}

// ======================= launch ==============================================
extern "C" void kernel_launch(void* const* d_in, const int* in_sizes, int n_in,
                              void* d_out, int out_size)
{
    const int*   ids     = (const int*)  d_in[0];
    const float* tok_emb = (const float*)d_in[1];
    const float* pos_emb = (const float*)d_in[2];
    const float* ln_w    = (const float*)d_in[3];
    const float* ln_b    = (const float*)d_in[4];
    const float* in_w    = (const float*)d_in[5];
    const float* in_b    = (const float*)d_in[6];
    const float* conv_w  = (const float*)d_in[7];
    const float* conv_b  = (const float*)d_in[8];
    const float* xproj_w = (const float*)d_in[9];
    const float* dt_w    = (const float*)d_in[10];
    const float* dt_b    = (const float*)d_in[11];
    const float* A_log   = (const float*)d_in[12];
    const float* Dv      = (const float*)d_in[13];
    const float* out_w   = (const float*)d_in[14];
    const float* out_b   = (const float*)d_in[15];
    const float* frac_w  = (const float*)d_in[16];
    const float* frac_b  = (const float*)d_in[17];
    const float* fln_w   = (const float*)d_in[18];
    const float* fln_b   = (const float*)d_in[19];

    float *hs, *proj, *u, *dbc, *acc;
    __nv_bfloat16 *winh, *winl, *wouth, *woutl, *wfrh, *wfrl;
    __nv_bfloat16 *ah, *al, *hsh, *hsl, *ybh, *ybl;
    cudaGetSymbolAddress((void**)&hs,   g_hs);
    cudaGetSymbolAddress((void**)&proj, g_proj);
    cudaGetSymbolAddress((void**)&u,    g_u);
    cudaGetSymbolAddress((void**)&dbc,  g_dbc);
    cudaGetSymbolAddress((void**)&acc,  g_acc);
    cudaGetSymbolAddress((void**)&winh,  g_win_h);
    cudaGetSymbolAddress((void**)&winl,  g_win_l);
    cudaGetSymbolAddress((void**)&wouth, g_wout_h);
    cudaGetSymbolAddress((void**)&woutl, g_wout_l);
    cudaGetSymbolAddress((void**)&wfrh,  g_wfr_h);
    cudaGetSymbolAddress((void**)&wfrl,  g_wfr_l);
    cudaGetSymbolAddress((void**)&ah,   g_ah);
    cudaGetSymbolAddress((void**)&al,   g_al);
    cudaGetSymbolAddress((void**)&hsh,  g_hsh);
    cudaGetSymbolAddress((void**)&hsl,  g_hsl);
    cudaGetSymbolAddress((void**)&ybh,  g_ybh);
    cudaGetSymbolAddress((void**)&ybl,  g_ybl);

    cudaFuncSetAttribute(mma_gemm<0,0,0,1,0>, cudaFuncAttributeMaxDynamicSharedMemorySize, GSMEM);
    cudaFuncSetAttribute(mma_gemm<0,0,1,1,1>, cudaFuncAttributeMaxDynamicSharedMemorySize, GSMEM);
    cudaFuncSetAttribute(mma_gemm<1,0,0,0,1>, cudaFuncAttributeMaxDynamicSharedMemorySize, GSMEM);
    cudaFuncSetAttribute(mma_gemm<1,0,0,1,0>, cudaFuncAttributeMaxDynamicSharedMemorySize, GSMEM);
    cudaFuncSetAttribute(mma_gemm<1,1,0,1,0>, cudaFuncAttributeMaxDynamicSharedMemorySize, GSMEM);

    // weight transpose + hi/lo split (all layers, once per launch)
    wtrans<<<dim3(TWO_E/32, Hd/32, NLY), dim3(32,8)>>>(in_w, winh, winl, Hd, TWO_E);
    wtrans<<<dim3(Hd/32, Ed/32, NLY),    dim3(32,8)>>>(out_w, wouth, woutl, Ed, Hd);
    wtrans<<<dim3(Hd/32, Hd/32, NLY*Cc), dim3(32,8)>>>(frac_w, wfrh, wfrl, Hd, Hd);

    embed_kernel<<<(Mrows*Hd + 255)/256, 256>>>(ids, tok_emb, pos_emb, hs);

    for (int l = 0; l < NLY; l++) {
        // x = LN(hs [+ acc/6]) -> (ah, al) bf16
        if (l == 0)
            ln_fused<0,1><<<Mrows, 256>>>(hs, nullptr,
                ln_w + (size_t)l*Hd, ln_b + (size_t)l*Hd, nullptr, ah, al);
        else
            ln_fused<1,1><<<Mrows, 256>>>(hs, acc,
                ln_w + (size_t)l*Hd, ln_b + (size_t)l*Hd, nullptr, ah, al);

        // proj = x @ in_w + in_b (fp32)
        mma_gemm<0,0,0,1,0><<<dim3(TWO_E/128, Mrows/128), 256, GSMEM>>>(
            ah, al, winh + (size_t)l*TWO_E*Hd, winl + (size_t)l*TWO_E*Hd,
            in_b + (size_t)l*TWO_E, nullptr, proj, nullptr, nullptr, Mrows, Hd, TWO_E);

        conv_silu<<<(Mrows*Ed + 255)/256, 256>>>(
            proj, conv_w + (size_t)l*Ed*Kc, conv_b + (size_t)l*Ed, u);

        xproj_kernel<<<Mrows/8, 256>>>(u, xproj_w + (size_t)l*Ed*DBC, dbc);

        // scan -> ys as (ah, al) bf16
        scan_kernel<<<192, 256>>>(u, dbc, proj,
            dt_w + (size_t)l*Rr*Ed, dt_b + (size_t)l*Ed,
            A_log + (size_t)l*Ed*Nst, Dv + (size_t)l*Ed, ah, al);

        // hs = ys @ out_w + out_b + hs (fp32) and (hsh, hsl) bf16
        mma_gemm<0,0,1,1,1><<<dim3(Hd/128, Mrows/128), 256, GSMEM>>>(
            ah, al, wouth + (size_t)l*Hd*Ed, woutl + (size_t)l*Hd*Ed,
            out_b + (size_t)l*Hd, hs, hs, hsh, hsl, Mrows, Ed, Hd);

        // fractal: acc = sum_i silu^3(hs)
        for (int i = 0; i < Cc; i++) {
            const __nv_bfloat16* fwh = wfrh + ((size_t)l*Cc + i)*Hd*Hd;
            const __nv_bfloat16* fwl = wfrl + ((size_t)l*Cc + i)*Hd*Hd;
            const float* fb = frac_b + ((size_t)l*Cc + i)*Hd;
            mma_gemm<1,0,0,0,1><<<dim3(Hd/128, Mrows/128), 256, GSMEM>>>(
                hsh, hsl, fwh, fwl, fb, nullptr, nullptr, ah, al, Mrows, Hd, Hd);
            mma_gemm<1,0,0,0,1><<<dim3(Hd/128, Mrows/128), 256, GSMEM>>>(
                ah, al, fwh, fwl, fb, nullptr, nullptr, ybh, ybl, Mrows, Hd, Hd);
            if (i == 0)
                mma_gemm<1,0,0,1,0><<<dim3(Hd/128, Mrows/128), 256, GSMEM>>>(
                    ybh, ybl, fwh, fwl, fb, nullptr, acc, nullptr, nullptr, Mrows, Hd, Hd);
            else
                mma_gemm<1,1,0,1,0><<<dim3(Hd/128, Mrows/128), 256, GSMEM>>>(
                    ybh, ybl, fwh, fwl, fb, nullptr, acc, nullptr, nullptr, Mrows, Hd, Hd);
        }
    }

    // final: hs += acc/6 ; out = LN(hs)
    ln_fused<1,0><<<Mrows, 256>>>(hs, acc, fln_w, fln_b, (float*)d_out, nullptr, nullptr);
}